// round 13
// baseline (speedup 1.0000x reference)
#include <cuda_runtime.h>
#include <math.h>

// Problem shape (fixed by dataset): B=32, L=8192, K=64, 20 amino acids.
#define B_DIM 32
#define L_DIM 8192
#define K_DIM 64
#define THREADS 256
#define WARPS (THREADS / 32)
#define ROWS_PER_STEP (WARPS * 2)          // 16 rows per step (2 rows/warp)
#define NSTEPS_TOTAL  (L_DIM / ROWS_PER_STEP)  // 512 steps per batch row
#define BLOCKS_PER_B 27                    // 32 x 27 = 864 blocks = 1 wave @ occ 6
#define STEP_STRIDE_ROWS (BLOCKS_PER_B * ROWS_PER_STEP)   // 432

__global__ __launch_bounds__(THREADS, 6)
void hp_pairs_kernel(const int* __restrict__ seq,
                     const float* __restrict__ r,
                     const int* __restrict__ j_idx,
                     const float* __restrict__ h,
                     const float* __restrict__ r_half_raw,
                     const float* __restrict__ tau_hp_raw,
                     const int* __restrict__ max_dist,
                     float* __restrict__ out)
{
    __shared__ float s_hseq[L_DIM];   // h[seq[b, :]] for this batch row (32 KB)

    const int b    = blockIdx.x;
    const int tblk = blockIdx.y;      // 0..26, step stride
    const int tid  = threadIdx.x;
    const int lane = tid & 31;
    const int warp = tid >> 5;

    // Each lane holds one h-table entry (20 entries <= 32 lanes).
    const float h_lane = h[min(lane, 19)];

    // Stage h[seq[b,:]] into smem ONCE per block: LDG.128 -> 4x shfl -> STS.128.
    {
        const int4* src = (const int4*)(seq + b * L_DIM);
        float4*     dst = (float4*)s_hseq;
        #pragma unroll
        for (int it = 0; it < L_DIM / 4 / THREADS; ++it) {
            int4 s4 = src[tid + it * THREADS];
            float4 v;
            v.x = __shfl_sync(0xffffffffu, h_lane, s4.x);
            v.y = __shfl_sync(0xffffffffu, h_lane, s4.y);
            v.z = __shfl_sync(0xffffffffu, h_lane, s4.z);
            v.w = __shfl_sync(0xffffffffu, h_lane, s4.w);
            dst[tid + it * THREADS] = v;
        }
    }

    // Scalars. g = exp(-(r-rp)^2/(2 s^2)) = 2^( qa*r^2 + qb*r + qc ), qa<0.
    const float md     = (float)(*max_dist);
    const float r_peak = log1pf(expf(*r_half_raw));
    const float sigma  = log1pf(expf(*tau_hp_raw)) + 0.1f;
    const float qa     = -1.44269504088896340736f / (2.0f * sigma * sigma);
    const float qb     = -2.0f * qa * r_peak;
    const float qc     = qa * r_peak * r_peak;
    const float thresh = md - 1e-4f;

    __syncthreads();

    // Mapping: 16 lanes per row, 2 rows per warp, 16 rows per step.
    const int l16  = lane & 15;               // k-chunk within row
    const int rsub = lane >> 4;               // which of the warp's 2 rows
    const int rowoff = warp * 2 + rsub;

    // Steps assigned round-robin: tblk, tblk+27, ... (19 or 18 steps/block).
    const int n = (NSTEPS_TOTAL - tblk + BLOCKS_PER_B - 1) / BLOCKS_PER_B;

    const int row_base = tblk * ROWS_PER_STEP + rowoff;
    const float* rp = r     + ((size_t)b * L_DIM + row_base) * K_DIM + l16 * 4;
    const int*   jp = j_idx + ((size_t)b * L_DIM + row_base) * K_DIM + l16 * 4;
    float*       ob = out   + (size_t)b * L_DIM;

    const size_t dstep = (size_t)STEP_STRIDE_ROWS * K_DIM;   // 27648 elements

    int4   j0, j1;
    float4 r0, r1;

#define LOADBUF(JV, RV)                          \
    do {                                         \
        (JV) = __ldcs((const int4*)jp);          \
        (RV) = __ldcs((const float4*)rp);        \
        jp += dstep; rp += dstep;                \
    } while (0)

#define CONSUME(JV, RV, ROW)                                            \
    do {                                                                \
        const float hj0 = s_hseq[(JV).x & (L_DIM - 1)];                 \
        const float hj1 = s_hseq[(JV).y & (L_DIM - 1)];                 \
        const float hj2 = s_hseq[(JV).z & (L_DIM - 1)];                 \
        const float hj3 = s_hseq[(JV).w & (L_DIM - 1)];                 \
        float t0 = fmaf(fmaf(qa, (RV).x, qb), (RV).x, qc);              \
        float t1 = fmaf(fmaf(qa, (RV).y, qb), (RV).y, qc);              \
        float t2 = fmaf(fmaf(qa, (RV).z, qb), (RV).z, qc);              \
        float t3 = fmaf(fmaf(qa, (RV).w, qb), (RV).w, qc);              \
        t0 = ((RV).x < thresh) ? t0 : -350.0f;                          \
        t1 = ((RV).y < thresh) ? t1 : -350.0f;                          \
        t2 = ((RV).z < thresh) ? t2 : -350.0f;                          \
        t3 = ((RV).w < thresh) ? t3 : -350.0f;                          \
        float g0, g1, g2, g3;                                           \
        asm("ex2.approx.ftz.f32 %0, %1;" : "=f"(g0) : "f"(t0));         \
        asm("ex2.approx.ftz.f32 %0, %1;" : "=f"(g1) : "f"(t1));         \
        asm("ex2.approx.ftz.f32 %0, %1;" : "=f"(g2) : "f"(t2));         \
        asm("ex2.approx.ftz.f32 %0, %1;" : "=f"(g3) : "f"(t3));         \
        float a0 = fmaf(hj1, g1, hj0 * g0);                             \
        float a1 = fmaf(hj3, g3, hj2 * g2);                             \
        float acc = a0 + a1;                                            \
        acc += __shfl_xor_sync(0xffffffffu, acc, 8);                    \
        acc += __shfl_xor_sync(0xffffffffu, acc, 4);                    \
        acc += __shfl_xor_sync(0xffffffffu, acc, 2);                    \
        acc += __shfl_xor_sync(0xffffffffu, acc, 1);                    \
        if (l16 == 0) ob[(ROW)] = s_hseq[(ROW)] * acc;                  \
    } while (0)

    int row_cur = row_base;

    // Software pipeline, depth 2, processed in pairs with epilogue.
    LOADBUF(j0, r0);
    int i = 0;
    while (i + 2 <= n) {
        LOADBUF(j1, r1);
        CONSUME(j0, r0, row_cur);
        row_cur += STEP_STRIDE_ROWS;
        if (i + 2 < n) LOADBUF(j0, r0);
        CONSUME(j1, r1, row_cur);
        row_cur += STEP_STRIDE_ROWS;
        i += 2;
    }
    if (i < n)   // odd step count: final step already in buf0
        CONSUME(j0, r0, row_cur);

#undef LOADBUF
#undef CONSUME
}

extern "C" void kernel_launch(void* const* d_in, const int* in_sizes, int n_in,
                              void* d_out, int out_size)
{
    // metadata order: seq, r, j_idx, h, r_half_raw, tau_hp_raw, max_dist
    const int*   seq        = (const int*)d_in[0];
    const float* r          = (const float*)d_in[1];
    const int*   j_idx      = (const int*)d_in[2];
    const float* h          = (const float*)d_in[3];
    const float* r_half_raw = (const float*)d_in[4];
    const float* tau_hp_raw = (const float*)d_in[5];
    const int*   max_dist   = (const int*)d_in[6];
    float*       out        = (float*)d_out;

    dim3 grid(B_DIM, BLOCKS_PER_B);   // 32 x 27 = 864 blocks = single wave @ occ 6
    hp_pairs_kernel<<<grid, THREADS>>>(seq, r, j_idx, h,
                                       r_half_raw, tau_hp_raw, max_dist, out);
}

// round 14
// speedup vs baseline: 1.0921x; 1.0921x over previous
#include <cuda_runtime.h>
#include <math.h>
#include <stdint.h>

// Problem shape (fixed by dataset): B=32, L=8192, K=64, 20 amino acids.
#define B_DIM 32
#define L_DIM 8192
#define K_DIM 64
#define THREADS 256
#define WARPS (THREADS / 32)
#define UNIT_ROWS 16
#define UNIT_ELEMS (UNIT_ROWS * K_DIM)       // 1024 elements = 4 KB per array
#define UNITS (L_DIM / UNIT_ROWS)            // 512 units per batch row
#define BPB 18                                // blocks per batch: 32x18=576 blocks
#define DEPTH 3                               // smem pipeline stages
#define HSEQ_BYTES (L_DIM * 4)                // 32 KB
#define STAGE_BYTES (UNIT_ELEMS * 4)          // 4 KB
#define SMEM_TOTAL (HSEQ_BYTES + DEPTH * STAGE_BYTES * 2)   // 57344 B

__device__ __forceinline__ void cp_async16(uint32_t dst, const void* src) {
    asm volatile("cp.async.cg.shared.global [%0], [%1], 16;" :: "r"(dst), "l"(src));
}
#define CP_COMMIT()  asm volatile("cp.async.commit_group;")
#define CP_WAIT(N)   asm volatile("cp.async.wait_group %0;" :: "n"(N))

__global__ __launch_bounds__(THREADS)
void hp_pairs_kernel(const int* __restrict__ seq,
                     const float* __restrict__ r,
                     const int* __restrict__ j_idx,
                     const float* __restrict__ h,
                     const float* __restrict__ r_half_raw,
                     const float* __restrict__ tau_hp_raw,
                     const int* __restrict__ max_dist,
                     float* __restrict__ out)
{
    extern __shared__ char smem[];
    float* s_hseq = (float*)smem;                                  // 32 KB
    float* s_rst  = (float*)(smem + HSEQ_BYTES);                   // [3][1024]
    int*   s_jst  = (int*)(smem + HSEQ_BYTES + DEPTH * STAGE_BYTES);

    const int b    = blockIdx.x;
    const int tblk = blockIdx.y;      // 0..BPB-1
    const int tid  = threadIdx.x;
    const int lane = tid & 31;
    const int warp = tid >> 5;

    const float* rb = r     + ((size_t)b * L_DIM) * K_DIM;
    const int*   jb = j_idx + ((size_t)b * L_DIM) * K_DIM;
    float*       ob = out   + (size_t)b * L_DIM;

    const uint32_t r_dst0 = (uint32_t)__cvta_generic_to_shared(s_rst) + tid * 16;
    const uint32_t j_dst0 = (uint32_t)__cvta_generic_to_shared(s_jst) + tid * 16;

    const int nu = (UNITS - tblk + BPB - 1) / BPB;   // 29 or 28 units

    // ---- prologue: start DRAM streaming IMMEDIATELY (no registers held) ----
    {
        int u0 = tblk;
        cp_async16(r_dst0, rb + (size_t)u0 * UNIT_ELEMS + tid * 4);
        cp_async16(j_dst0, jb + (size_t)u0 * UNIT_ELEMS + tid * 4);
        CP_COMMIT();
        int u1 = tblk + BPB;
        cp_async16(r_dst0 + STAGE_BYTES, rb + (size_t)u1 * UNIT_ELEMS + tid * 4);
        cp_async16(j_dst0 + STAGE_BYTES, jb + (size_t)u1 * UNIT_ELEMS + tid * 4);
        CP_COMMIT();
    }

    // ---- stage h[seq[b,:]] into smem (overlaps with cp.async stream) ----
    const float h_lane = h[min(lane, 19)];
    {
        const int4* src = (const int4*)(seq + b * L_DIM);
        float4*     dst = (float4*)s_hseq;
        #pragma unroll
        for (int it = 0; it < L_DIM / 4 / THREADS; ++it) {
            int4 s4 = src[tid + it * THREADS];
            float4 v;
            v.x = __shfl_sync(0xffffffffu, h_lane, s4.x);
            v.y = __shfl_sync(0xffffffffu, h_lane, s4.y);
            v.z = __shfl_sync(0xffffffffu, h_lane, s4.z);
            v.w = __shfl_sync(0xffffffffu, h_lane, s4.w);
            dst[tid + it * THREADS] = v;
        }
    }

    // Scalars. g = exp(-(r-rp)^2/(2 s^2)) = 2^( qa*r^2 + qb*r + qc ), qa<0.
    const float md     = (float)(*max_dist);
    const float r_peak = log1pf(expf(*r_half_raw));
    const float sigma  = log1pf(expf(*tau_hp_raw)) + 0.1f;
    const float qa     = -1.44269504088896340736f / (2.0f * sigma * sigma);
    const float qb     = -2.0f * qa * r_peak;
    const float qc     = qa * r_peak * r_peak;
    const float thresh = md - 1e-4f;

    // Consumer mapping: 16 lanes/row, 2 rows/warp, 16 rows/unit.
    const int l16  = lane & 15;
    const int rsub = lane >> 4;
    const int row_in_unit = warp * 2 + rsub;
    const int soff = row_in_unit * K_DIM + l16 * 4;   // element offset in stage

    int buf = 0;
    for (int s = 0; s < nu; ++s) {
        // stage s ready? (groups complete in order; last 2 iters need full drain)
        if (s + 2 < nu) { CP_WAIT(1); } else { CP_WAIT(0); }
        __syncthreads();   // data visible to all; all done consuming stage s-1

        // refill: issue stage s+2 into the buffer consumed at step s-1
        if (s + 2 < nu) {
            const int u2   = tblk + (s + 2) * BPB;
            const int buf2 = (s + 2) % DEPTH;
            cp_async16(r_dst0 + buf2 * STAGE_BYTES, rb + (size_t)u2 * UNIT_ELEMS + tid * 4);
            cp_async16(j_dst0 + buf2 * STAGE_BYTES, jb + (size_t)u2 * UNIT_ELEMS + tid * 4);
            CP_COMMIT();
        }

        // ---- consume stage s from smem (conflict-free LDS.128) ----
        const int base = buf * UNIT_ELEMS + soff;
        const float4 rv = *(const float4*)(s_rst + base);
        const int4   jv = *(const int4*)(s_jst + base);

        const float hj0 = s_hseq[jv.x & (L_DIM - 1)];
        const float hj1 = s_hseq[jv.y & (L_DIM - 1)];
        const float hj2 = s_hseq[jv.z & (L_DIM - 1)];
        const float hj3 = s_hseq[jv.w & (L_DIM - 1)];

        float t0 = fmaf(fmaf(qa, rv.x, qb), rv.x, qc);
        float t1 = fmaf(fmaf(qa, rv.y, qb), rv.y, qc);
        float t2 = fmaf(fmaf(qa, rv.z, qb), rv.z, qc);
        float t3 = fmaf(fmaf(qa, rv.w, qb), rv.w, qc);
        t0 = (rv.x < thresh) ? t0 : -350.0f;     // invalid -> 2^-350 -> 0
        t1 = (rv.y < thresh) ? t1 : -350.0f;
        t2 = (rv.z < thresh) ? t2 : -350.0f;
        t3 = (rv.w < thresh) ? t3 : -350.0f;

        float g0, g1, g2, g3;
        asm("ex2.approx.ftz.f32 %0, %1;" : "=f"(g0) : "f"(t0));
        asm("ex2.approx.ftz.f32 %0, %1;" : "=f"(g1) : "f"(t1));
        asm("ex2.approx.ftz.f32 %0, %1;" : "=f"(g2) : "f"(t2));
        asm("ex2.approx.ftz.f32 %0, %1;" : "=f"(g3) : "f"(t3));

        float a0 = fmaf(hj1, g1, hj0 * g0);
        float a1 = fmaf(hj3, g3, hj2 * g2);
        float acc = a0 + a1;

        // reduce across the 16 lanes of this row
        acc += __shfl_xor_sync(0xffffffffu, acc, 8);
        acc += __shfl_xor_sync(0xffffffffu, acc, 4);
        acc += __shfl_xor_sync(0xffffffffu, acc, 2);
        acc += __shfl_xor_sync(0xffffffffu, acc, 1);

        const int row = (tblk + s * BPB) * UNIT_ROWS + row_in_unit;
        if (l16 == 0)
            ob[row] = s_hseq[row] * acc;

        buf = (buf == DEPTH - 1) ? 0 : buf + 1;
    }
}

extern "C" void kernel_launch(void* const* d_in, const int* in_sizes, int n_in,
                              void* d_out, int out_size)
{
    // metadata order: seq, r, j_idx, h, r_half_raw, tau_hp_raw, max_dist
    const int*   seq        = (const int*)d_in[0];
    const float* r          = (const float*)d_in[1];
    const int*   j_idx      = (const int*)d_in[2];
    const float* h          = (const float*)d_in[3];
    const float* r_half_raw = (const float*)d_in[4];
    const float* tau_hp_raw = (const float*)d_in[5];
    const int*   max_dist   = (const int*)d_in[6];
    float*       out        = (float*)d_out;

    cudaFuncSetAttribute(hp_pairs_kernel,
                         cudaFuncAttributeMaxDynamicSharedMemorySize, SMEM_TOTAL);

    dim3 grid(B_DIM, BPB);   // 32 x 18 = 576 blocks, 4 CTAs/SM (smem-limited)
    hp_pairs_kernel<<<grid, THREADS, SMEM_TOTAL>>>(seq, r, j_idx, h,
                                                   r_half_raw, tau_hp_raw,
                                                   max_dist, out);
}

// round 15
// speedup vs baseline: 1.2042x; 1.1027x over previous
#include <cuda_runtime.h>
#include <math.h>
#include <stdint.h>

// Problem shape (fixed by dataset): B=32, L=8192, K=64, 20 amino acids.
#define B_DIM 32
#define L_DIM 8192
#define K_DIM 64
#define THREADS 256
#define WARPS (THREADS / 32)
#define BPB 18                                // blocks per batch: 32x18 = 576
#define WPB_BATCH (BPB * WARPS)               // 144 warp-streams per batch
#define UNIT_ROWS 2
#define UNIT_ELEMS (UNIT_ROWS * K_DIM)        // 128 elements = 512 B per array
#define UNIT_BYTES (UNIT_ELEMS * 4)           // 512
#define N_UNITS (L_DIM / UNIT_ROWS)           // 4096 units per batch row
#define DEPTH 3                               // per-warp ring slots
#define HSEQ_BYTES (L_DIM * 4)                // 32 KB
#define RING_BYTES (WARPS * DEPTH * UNIT_BYTES)   // 12 KB per array
#define SMEM_TOTAL (HSEQ_BYTES + 2 * RING_BYTES)  // 56 KB -> 4 CTAs/SM

__device__ __forceinline__ void cp_async16(uint32_t dst, const void* src) {
    asm volatile("cp.async.cg.shared.global [%0], [%1], 16;" :: "r"(dst), "l"(src));
}
#define CP_COMMIT()  asm volatile("cp.async.commit_group;")
#define CP_WAIT(N)   asm volatile("cp.async.wait_group %0;" :: "n"(N))

__global__ __launch_bounds__(THREADS)
void hp_pairs_kernel(const int* __restrict__ seq,
                     const float* __restrict__ r,
                     const int* __restrict__ j_idx,
                     const float* __restrict__ h,
                     const float* __restrict__ r_half_raw,
                     const float* __restrict__ tau_hp_raw,
                     const int* __restrict__ max_dist,
                     float* __restrict__ out)
{
    extern __shared__ char smem[];
    float* s_hseq = (float*)smem;                                  // 32 KB

    const int b    = blockIdx.x;
    const int tblk = blockIdx.y;      // 0..BPB-1
    const int tid  = threadIdx.x;
    const int lane = tid & 31;
    const int warp = tid >> 5;

    const float* rb = r     + ((size_t)b * L_DIM) * K_DIM;
    const int*   jb = j_idx + ((size_t)b * L_DIM) * K_DIM;
    float*       ob = out   + (size_t)b * L_DIM;

    // Per-warp ring bases (shared addresses), lane-offset baked in.
    const uint32_t smem_base = (uint32_t)__cvta_generic_to_shared(smem);
    const uint32_t r_ring = smem_base + HSEQ_BYTES
                          + warp * (DEPTH * UNIT_BYTES) + lane * 16;
    const uint32_t j_ring = smem_base + HSEQ_BYTES + RING_BYTES
                          + warp * (DEPTH * UNIT_BYTES) + lane * 16;
    float* s_rring = (float*)(smem + HSEQ_BYTES
                          + warp * (DEPTH * UNIT_BYTES));
    int*   s_jring = (int*)(smem + HSEQ_BYTES + RING_BYTES
                          + warp * (DEPTH * UNIT_BYTES));

    // This warp's unit stream: w, w+144, ... (29 or 28 units).
    const int w  = tblk * WARPS + warp;
    const int n  = (N_UNITS - w + WPB_BATCH - 1) / WPB_BATCH;

    // ---- prologue: 2 stages in flight BEFORE anything else ----
    {
        const size_t e0 = (size_t)w * UNIT_ELEMS + lane * 4;
        cp_async16(r_ring + 0 * UNIT_BYTES, rb + e0);
        cp_async16(j_ring + 0 * UNIT_BYTES, jb + e0);
        CP_COMMIT();
        const size_t e1 = e0 + (size_t)WPB_BATCH * UNIT_ELEMS;
        cp_async16(r_ring + 1 * UNIT_BYTES, rb + e1);
        cp_async16(j_ring + 1 * UNIT_BYTES, jb + e1);
        CP_COMMIT();
    }

    // ---- stage h[seq[b,:]] into smem (overlaps the cp.async stream) ----
    const float h_lane = h[min(lane, 19)];
    {
        const int4* src = (const int4*)(seq + b * L_DIM);
        float4*     dst = (float4*)s_hseq;
        #pragma unroll
        for (int it = 0; it < L_DIM / 4 / THREADS; ++it) {
            int4 s4 = src[tid + it * THREADS];
            float4 v;
            v.x = __shfl_sync(0xffffffffu, h_lane, s4.x);
            v.y = __shfl_sync(0xffffffffu, h_lane, s4.y);
            v.z = __shfl_sync(0xffffffffu, h_lane, s4.z);
            v.w = __shfl_sync(0xffffffffu, h_lane, s4.w);
            dst[tid + it * THREADS] = v;
        }
    }

    // Scalars. g = exp(-(r-rp)^2/(2 s^2)) = 2^( qa*r^2 + qb*r + qc ), qa<0.
    const float md     = (float)(*max_dist);
    const float r_peak = log1pf(expf(*r_half_raw));
    const float sigma  = log1pf(expf(*tau_hp_raw)) + 0.1f;
    const float qa     = -1.44269504088896340736f / (2.0f * sigma * sigma);
    const float qb     = -2.0f * qa * r_peak;
    const float qc     = qa * r_peak * r_peak;
    const float thresh = md - 1e-4f;

    __syncthreads();   // hseq visible; the ONLY block barrier

    // Consumer mapping: 16 lanes per row, 2 rows per unit.
    const int l16  = lane & 15;
    const int rsub = lane >> 4;
    const int soff = rsub * K_DIM + l16 * 4;   // element offset within unit

    int slot = 0;
    int u    = w;                              // current unit index
    for (int i = 0; i < n; ++i) {
        // oldest pending stage (unit i) complete?
        if (i < n - 1) { CP_WAIT(1); } else { CP_WAIT(0); }

        // refill: issue unit i+2 into the slot freed at step i-1
        if (i + 2 < n) {
            const int s2 = (i + 2) % DEPTH;
            const size_t e2 = ((size_t)u + 2 * WPB_BATCH) * UNIT_ELEMS + lane * 4;
            cp_async16(r_ring + s2 * UNIT_BYTES, rb + e2);
            cp_async16(j_ring + s2 * UNIT_BYTES, jb + e2);
            CP_COMMIT();
        }

        // ---- consume unit i from this warp's ring (conflict-free LDS.128) ----
        const int base = slot * UNIT_ELEMS + soff;
        const float4 rv = *(const float4*)(s_rring + base);
        const int4   jv = *(const int4*)(s_jring + base);

        const float hj0 = s_hseq[jv.x & (L_DIM - 1)];
        const float hj1 = s_hseq[jv.y & (L_DIM - 1)];
        const float hj2 = s_hseq[jv.z & (L_DIM - 1)];
        const float hj3 = s_hseq[jv.w & (L_DIM - 1)];

        float t0 = fmaf(fmaf(qa, rv.x, qb), rv.x, qc);
        float t1 = fmaf(fmaf(qa, rv.y, qb), rv.y, qc);
        float t2 = fmaf(fmaf(qa, rv.z, qb), rv.z, qc);
        float t3 = fmaf(fmaf(qa, rv.w, qb), rv.w, qc);
        t0 = (rv.x < thresh) ? t0 : -350.0f;     // invalid -> 2^-350 -> 0
        t1 = (rv.y < thresh) ? t1 : -350.0f;
        t2 = (rv.z < thresh) ? t2 : -350.0f;
        t3 = (rv.w < thresh) ? t3 : -350.0f;

        float g0, g1, g2, g3;
        asm("ex2.approx.ftz.f32 %0, %1;" : "=f"(g0) : "f"(t0));
        asm("ex2.approx.ftz.f32 %0, %1;" : "=f"(g1) : "f"(t1));
        asm("ex2.approx.ftz.f32 %0, %1;" : "=f"(g2) : "f"(t2));
        asm("ex2.approx.ftz.f32 %0, %1;" : "=f"(g3) : "f"(t3));

        float a0 = fmaf(hj1, g1, hj0 * g0);
        float a1 = fmaf(hj3, g3, hj2 * g2);
        float acc = a0 + a1;

        // reduce across the 16 lanes of this row
        acc += __shfl_xor_sync(0xffffffffu, acc, 8);
        acc += __shfl_xor_sync(0xffffffffu, acc, 4);
        acc += __shfl_xor_sync(0xffffffffu, acc, 2);
        acc += __shfl_xor_sync(0xffffffffu, acc, 1);

        const int row = u * UNIT_ROWS + rsub;
        if (l16 == 0)
            ob[row] = s_hseq[row] * acc;

        slot = (slot == DEPTH - 1) ? 0 : slot + 1;
        u   += WPB_BATCH;
    }
}

extern "C" void kernel_launch(void* const* d_in, const int* in_sizes, int n_in,
                              void* d_out, int out_size)
{
    // metadata order: seq, r, j_idx, h, r_half_raw, tau_hp_raw, max_dist
    const int*   seq        = (const int*)d_in[0];
    const float* r          = (const float*)d_in[1];
    const int*   j_idx      = (const int*)d_in[2];
    const float* h          = (const float*)d_in[3];
    const float* r_half_raw = (const float*)d_in[4];
    const float* tau_hp_raw = (const float*)d_in[5];
    const int*   max_dist   = (const int*)d_in[6];
    float*       out        = (float*)d_out;

    cudaFuncSetAttribute(hp_pairs_kernel,
                         cudaFuncAttributeMaxDynamicSharedMemorySize, SMEM_TOTAL);

    dim3 grid(B_DIM, BPB);   // 32 x 18 = 576 blocks, 4 CTAs/SM
    hp_pairs_kernel<<<grid, THREADS, SMEM_TOTAL>>>(seq, r, j_idx, h,
                                                   r_half_raw, tau_hp_raw,
                                                   max_dist, out);
}

// round 16
// speedup vs baseline: 1.2170x; 1.0106x over previous
#include <cuda_runtime.h>
#include <math.h>

// Problem shape (fixed by dataset): B=32, L=8192, K=64, 20 amino acids.
#define B_DIM 32
#define L_DIM 8192
#define K_DIM 64
#define THREADS 256
#define WARPS (THREADS / 32)
#define ROWS_PER_U  (WARPS * 4)            // 32 rows per u-step
#define CHUNK_ROWS  (ROWS_PER_U * 2)       // 64 rows per chunk
#define N_CHUNKS    (L_DIM / CHUNK_ROWS)   // 128 chunks per batch row
#define BLOCKS_PER_B 23                    // 32 x 23 = 736 blocks = 1 wave @ occ 5
#define CHUNK_STRIDE_ROWS (BLOCKS_PER_B * CHUNK_ROWS)   // 1472

// Streaming loads with 256B L2 fetch promotion: the first request for a
// 256B-aligned row pulls the whole row into L2; the paired load hits L2.
__device__ __forceinline__ float4 ldcs256_f4(const float* p) {
    float4 v;
    asm("ld.global.cs.L2::256B.v4.f32 {%0,%1,%2,%3}, [%4];"
        : "=f"(v.x), "=f"(v.y), "=f"(v.z), "=f"(v.w) : "l"(p));
    return v;
}
__device__ __forceinline__ int4 ldcs256_i4(const int* p) {
    int4 v;
    asm("ld.global.cs.L2::256B.v4.u32 {%0,%1,%2,%3}, [%4];"
        : "=r"(v.x), "=r"(v.y), "=r"(v.z), "=r"(v.w) : "l"(p));
    return v;
}
__device__ __forceinline__ void stcs_f(float* p, float v) {
    asm volatile("st.global.cs.f32 [%0], %1;" :: "l"(p), "f"(v));
}

__global__ __launch_bounds__(THREADS, 5)
void hp_pairs_kernel(const int* __restrict__ seq,
                     const float* __restrict__ r,
                     const int* __restrict__ j_idx,
                     const float* __restrict__ h,
                     const float* __restrict__ r_half_raw,
                     const float* __restrict__ tau_hp_raw,
                     const int* __restrict__ max_dist,
                     float* __restrict__ out)
{
    __shared__ float s_hseq[L_DIM];   // h[seq[b, :]] for this batch row (32 KB)

    const int b    = blockIdx.x;
    const int tblk = blockIdx.y;      // 0..22
    const int tid  = threadIdx.x;
    const int lane = tid & 31;
    const int warp = tid >> 5;

    // Each lane holds one h-table entry (20 entries <= 32 lanes).
    const float h_lane = h[min(lane, 19)];

    // Stage h[seq[b,:]] into smem ONCE per block: LDG.128 -> 4x shfl -> STS.128.
    {
        const int4* src = (const int4*)(seq + b * L_DIM);
        float4*     dst = (float4*)s_hseq;
        #pragma unroll
        for (int it = 0; it < L_DIM / 4 / THREADS; ++it) {
            int4 s4 = src[tid + it * THREADS];
            float4 v;
            v.x = __shfl_sync(0xffffffffu, h_lane, s4.x);
            v.y = __shfl_sync(0xffffffffu, h_lane, s4.y);
            v.z = __shfl_sync(0xffffffffu, h_lane, s4.z);
            v.w = __shfl_sync(0xffffffffu, h_lane, s4.w);
            dst[tid + it * THREADS] = v;
        }
    }

    // Scalars. g = exp(-(r-rp)^2/(2 s^2)) = 2^( qa*r^2 + qb*r + qc ), qa<0.
    const float md     = (float)(*max_dist);
    const float r_peak = log1pf(expf(*r_half_raw));
    const float sigma  = log1pf(expf(*tau_hp_raw)) + 0.1f;
    const float qa     = -1.44269504088896340736f / (2.0f * sigma * sigma);
    const float qb     = -2.0f * qa * r_peak;
    const float qc     = qa * r_peak * r_peak;
    const float thresh = md - 1e-4f;

    __syncthreads();

    // Mapping: 8 lanes per row, 4 rows per warp, 32 rows per u-step.
    const int l8   = lane & 7;
    const int rgrp = lane >> 3;
    const int rowoff = warp * 4 + rgrp;

    const int nchunks = (N_CHUNKS - tblk + BLOCKS_PER_B - 1) / BLOCKS_PER_B;
    const int nsteps  = nchunks * 2;            // always even

    const int row_base = tblk * CHUNK_ROWS + rowoff;
    const float* rp = r     + ((size_t)b * L_DIM + row_base) * K_DIM + l8 * 4;
    const int*   jp = j_idx + ((size_t)b * L_DIM + row_base) * K_DIM + l8 * 4;
    float*       ob = out   + (size_t)b * L_DIM;

    // Step deltas (elements): u0->u1 within chunk, u1->u0 of next chunk.
    const size_t d0 = (size_t)ROWS_PER_U * K_DIM;                          // 2048
    const size_t d1 = (size_t)(CHUNK_STRIDE_ROWS - ROWS_PER_U) * K_DIM;    // 92160

    // Double buffers (compile-time parity, no dynamic indexing).
    float4 ra0[2], ra1[2];
    int4   ja0[2], ja1[2];

#define LOADBUF(JA, RA, JP, RP)                 \
    do {                                        \
        (JA)[0] = ldcs256_i4((JP));             \
        (JA)[1] = ldcs256_i4((JP) + 32);        \
        (RA)[0] = ldcs256_f4((RP));             \
        (RA)[1] = ldcs256_f4((RP) + 32);        \
    } while (0)

#define CONSUME(JA, RA, ROW)                                            \
    do {                                                                \
        float hj[8];                                                    \
        hj[0] = s_hseq[(JA)[0].x & (L_DIM - 1)];                        \
        hj[1] = s_hseq[(JA)[0].y & (L_DIM - 1)];                        \
        hj[2] = s_hseq[(JA)[0].z & (L_DIM - 1)];                        \
        hj[3] = s_hseq[(JA)[0].w & (L_DIM - 1)];                        \
        hj[4] = s_hseq[(JA)[1].x & (L_DIM - 1)];                        \
        hj[5] = s_hseq[(JA)[1].y & (L_DIM - 1)];                        \
        hj[6] = s_hseq[(JA)[1].z & (L_DIM - 1)];                        \
        hj[7] = s_hseq[(JA)[1].w & (L_DIM - 1)];                        \
        float rv[8] = { (RA)[0].x, (RA)[0].y, (RA)[0].z, (RA)[0].w,     \
                        (RA)[1].x, (RA)[1].y, (RA)[1].z, (RA)[1].w };   \
        float g[8];                                                     \
        _Pragma("unroll")                                               \
        for (int e = 0; e < 8; ++e) {                                   \
            float t = fmaf(fmaf(qa, rv[e], qb), rv[e], qc);             \
            t = (rv[e] < thresh) ? t : -350.0f;                         \
            asm("ex2.approx.ftz.f32 %0, %1;" : "=f"(g[e]) : "f"(t));    \
        }                                                               \
        float a0 = hj[0] * g[0], a1 = hj[1] * g[1];                     \
        a0 = fmaf(hj[2], g[2], a0);  a1 = fmaf(hj[3], g[3], a1);        \
        a0 = fmaf(hj[4], g[4], a0);  a1 = fmaf(hj[5], g[5], a1);        \
        a0 = fmaf(hj[6], g[6], a0);  a1 = fmaf(hj[7], g[7], a1);        \
        float acc = a0 + a1;                                            \
        acc += __shfl_xor_sync(0xffffffffu, acc, 4);                    \
        acc += __shfl_xor_sync(0xffffffffu, acc, 2);                    \
        acc += __shfl_xor_sync(0xffffffffu, acc, 1);                    \
        if (l8 == 0) stcs_f(ob + (ROW), s_hseq[(ROW)] * acc);           \
    } while (0)

    // Prologue: load step 0 (even), advance to step 1's position.
    LOADBUF(ja0, ra0, jp, rp);
    rp += d0; jp += d0;
    int row_cur = row_base;

    for (int s = 0; s < nsteps; s += 2) {
        // prefetch step s+1 (odd) into buf1; advance to step s+2
        LOADBUF(ja1, ra1, jp, rp);
        rp += d1; jp += d1;

        // consume step s (buf0)
        CONSUME(ja0, ra0, row_cur);
        row_cur += ROWS_PER_U;

        // prefetch step s+2 (even) into buf0; advance to step s+3
        if (s + 2 < nsteps) {
            LOADBUF(ja0, ra0, jp, rp);
            rp += d0; jp += d0;
        }

        // consume step s+1 (buf1)
        CONSUME(ja1, ra1, row_cur);
        row_cur += CHUNK_STRIDE_ROWS - ROWS_PER_U;
    }

#undef LOADBUF
#undef CONSUME
}

extern "C" void kernel_launch(void* const* d_in, const int* in_sizes, int n_in,
                              void* d_out, int out_size)
{
    // metadata order: seq, r, j_idx, h, r_half_raw, tau_hp_raw, max_dist
    const int*   seq        = (const int*)d_in[0];
    const float* r          = (const float*)d_in[1];
    const int*   j_idx      = (const int*)d_in[2];
    const float* h          = (const float*)d_in[3];
    const float* r_half_raw = (const float*)d_in[4];
    const float* tau_hp_raw = (const float*)d_in[5];
    const int*   max_dist   = (const int*)d_in[6];
    float*       out        = (float*)d_out;

    dim3 grid(B_DIM, BLOCKS_PER_B);   // 32 x 23 = 736 blocks = single wave
    hp_pairs_kernel<<<grid, THREADS>>>(seq, r, j_idx, h,
                                       r_half_raw, tau_hp_raw, max_dist, out);
}

// round 17
// speedup vs baseline: 1.2184x; 1.0012x over previous
#include <cuda_runtime.h>
#include <math.h>
#include <stdint.h>

// Problem shape (fixed by dataset): B=32, L=8192, K=64, 20 amino acids.
#define B_DIM 32
#define L_DIM 8192
#define K_DIM 64
#define THREADS 256
#define WARPS (THREADS / 32)
#define ROWS_PER_STEP (WARPS * 4)          // 32 rows per step
#define NSTEPS (L_DIM / ROWS_PER_STEP)     // 256 steps per batch row
#define BPB 23                             // 32 x 23 = 736 blocks = 1 wave @ occ 5
#define STRIDE_ROWS (BPB * ROWS_PER_STEP)  // 736 rows between a block's steps
#define STRIDE_ELEMS ((size_t)STRIDE_ROWS * K_DIM)

__device__ __forceinline__ float4 ldcs256_f4(const float* p) {
    float4 v;
    asm("ld.global.cs.L2::256B.v4.f32 {%0,%1,%2,%3}, [%4];"
        : "=f"(v.x), "=f"(v.y), "=f"(v.z), "=f"(v.w) : "l"(p));
    return v;
}
__device__ __forceinline__ int4 ldcs256_i4(const int* p) {
    int4 v;
    asm("ld.global.cs.L2::256B.v4.u32 {%0,%1,%2,%3}, [%4];"
        : "=r"(v.x), "=r"(v.y), "=r"(v.z), "=r"(v.w) : "l"(p));
    return v;
}
__device__ __forceinline__ void stcs_f(float* p, float v) {
    asm volatile("st.global.cs.f32 [%0], %1;" :: "l"(p), "f"(v));
}
__device__ __forceinline__ void cp_async16(uint32_t dst, const void* src) {
    asm volatile("cp.async.ca.shared.global [%0], [%1], 16;" :: "r"(dst), "l"(src));
}

__global__ __launch_bounds__(THREADS, 5)
void hp_pairs_kernel(const int* __restrict__ seq,
                     const float* __restrict__ r,
                     const int* __restrict__ j_idx,
                     const float* __restrict__ h,
                     const float* __restrict__ r_half_raw,
                     const float* __restrict__ tau_hp_raw,
                     const int* __restrict__ max_dist,
                     float* __restrict__ out)
{
    __shared__ int s_seq[L_DIM];      // raw seq[b,:] (32 KB); translated at consume

    const int b    = blockIdx.x;
    const int tblk = blockIdx.y;      // 0..22
    const int tid  = threadIdx.x;
    const int lane = tid & 31;
    const int warp = tid >> 5;

    // Each lane holds one h-table entry (20 entries <= 32 lanes).
    const float h_lane = h[min(lane, 19)];

    // ---- register-free staging: seq row -> smem via cp.async (no shfl chain) ----
    {
        const uint32_t dst0 = (uint32_t)__cvta_generic_to_shared(s_seq) + tid * 16;
        const int* src0 = seq + b * L_DIM + tid * 4;
        #pragma unroll
        for (int it = 0; it < L_DIM / 4 / THREADS; ++it)
            cp_async16(dst0 + it * (THREADS * 16), src0 + it * (THREADS * 4));
        asm volatile("cp.async.commit_group;");
    }

    // Mapping: 8 lanes per row, 4 rows per warp, 32 rows per step.
    const int l8   = lane & 7;
    const int rgrp = lane >> 3;
    const int row_base = tblk * ROWS_PER_STEP + warp * 4 + rgrp;

    const float* rp = r + ((size_t)b * L_DIM + row_base) * K_DIM + l8 * 4;
    const ptrdiff_t jd = (const char*)j_idx - (const char*)r;   // r -> j_idx delta
    float* ob = out + (size_t)b * L_DIM;

    const int n = (NSTEPS - tblk + BPB - 1) / BPB;   // 12 (tblk<3) or 11 steps

    // Double buffers; both steps' loads issued BEFORE the staging barrier.
    float4 ra0[2], ra1[2];
    int4   ja0[2], ja1[2];

#define LOADBUF(JA, RA, RP)                                              \
    do {                                                                 \
        const int* _jp = (const int*)((const char*)(RP) + jd);           \
        (JA)[0] = ldcs256_i4(_jp);                                       \
        (JA)[1] = ldcs256_i4(_jp + 32);                                  \
        (RA)[0] = ldcs256_f4((RP));                                      \
        (RA)[1] = ldcs256_f4((RP) + 32);                                 \
    } while (0)

    LOADBUF(ja0, ra0, rp);               // step 0  — DRAM streams from cycle ~0
    LOADBUF(ja1, ra1, rp + STRIDE_ELEMS); // step 1
    rp += 2 * STRIDE_ELEMS;

    // Scalars. g = exp(-(r-rp)^2/(2 s^2)) = 2^( qa*r^2 + qb*r + qc ), qa<0.
    const float md     = (float)(*max_dist);
    const float r_peak = log1pf(expf(*r_half_raw));
    const float sigma  = log1pf(expf(*tau_hp_raw)) + 0.1f;
    const float qa     = -1.44269504088896340736f / (2.0f * sigma * sigma);
    const float qb     = -2.0f * qa * r_peak;
    const float qc     = qa * r_peak * r_peak;
    const float thresh = md - 1e-4f;

    asm volatile("cp.async.wait_group 0;");
    __syncthreads();                     // s_seq visible to all warps

#define CONSUME(JA, RA, ROW)                                            \
    do {                                                                \
        int sj[8];                                                      \
        sj[0] = s_seq[(JA)[0].x & (L_DIM - 1)];                         \
        sj[1] = s_seq[(JA)[0].y & (L_DIM - 1)];                         \
        sj[2] = s_seq[(JA)[0].z & (L_DIM - 1)];                         \
        sj[3] = s_seq[(JA)[0].w & (L_DIM - 1)];                         \
        sj[4] = s_seq[(JA)[1].x & (L_DIM - 1)];                         \
        sj[5] = s_seq[(JA)[1].y & (L_DIM - 1)];                         \
        sj[6] = s_seq[(JA)[1].z & (L_DIM - 1)];                         \
        sj[7] = s_seq[(JA)[1].w & (L_DIM - 1)];                         \
        float hj[8];                                                    \
        _Pragma("unroll")                                               \
        for (int e = 0; e < 8; ++e)                                     \
            hj[e] = __shfl_sync(0xffffffffu, h_lane, sj[e]);            \
        float rv[8] = { (RA)[0].x, (RA)[0].y, (RA)[0].z, (RA)[0].w,     \
                        (RA)[1].x, (RA)[1].y, (RA)[1].z, (RA)[1].w };   \
        float g[8];                                                     \
        _Pragma("unroll")                                               \
        for (int e = 0; e < 8; ++e) {                                   \
            float t = fmaf(fmaf(qa, rv[e], qb), rv[e], qc);             \
            t = (rv[e] < thresh) ? t : -350.0f;                         \
            asm("ex2.approx.ftz.f32 %0, %1;" : "=f"(g[e]) : "f"(t));    \
        }                                                               \
        float a0 = hj[0] * g[0], a1 = hj[1] * g[1];                     \
        a0 = fmaf(hj[2], g[2], a0);  a1 = fmaf(hj[3], g[3], a1);        \
        a0 = fmaf(hj[4], g[4], a0);  a1 = fmaf(hj[5], g[5], a1);        \
        a0 = fmaf(hj[6], g[6], a0);  a1 = fmaf(hj[7], g[7], a1);        \
        float acc = a0 + a1;                                            \
        acc += __shfl_xor_sync(0xffffffffu, acc, 4);                    \
        acc += __shfl_xor_sync(0xffffffffu, acc, 2);                    \
        acc += __shfl_xor_sync(0xffffffffu, acc, 1);                    \
        const float hi = __shfl_sync(0xffffffffu, h_lane, s_seq[(ROW)]);\
        if (l8 == 0) stcs_f(ob + (ROW), hi * acc);                      \
    } while (0)

    int row_cur = row_base;
    int s = 0;
    while (s + 2 <= n) {
        CONSUME(ja0, ra0, row_cur);               // step s
        if (s + 2 < n) { LOADBUF(ja0, ra0, rp); rp += STRIDE_ELEMS; }
        row_cur += STRIDE_ROWS;
        CONSUME(ja1, ra1, row_cur);               // step s+1
        if (s + 3 < n) { LOADBUF(ja1, ra1, rp); rp += STRIDE_ELEMS; }
        row_cur += STRIDE_ROWS;
        s += 2;
    }
    if (s < n)                                    // odd n: final step in buf0
        CONSUME(ja0, ra0, row_cur);

#undef LOADBUF
#undef CONSUME
}

extern "C" void kernel_launch(void* const* d_in, const int* in_sizes, int n_in,
                              void* d_out, int out_size)
{
    // metadata order: seq, r, j_idx, h, r_half_raw, tau_hp_raw, max_dist
    const int*   seq        = (const int*)d_in[0];
    const float* r          = (const float*)d_in[1];
    const int*   j_idx      = (const int*)d_in[2];
    const float* h          = (const float*)d_in[3];
    const float* r_half_raw = (const float*)d_in[4];
    const float* tau_hp_raw = (const float*)d_in[5];
    const int*   max_dist   = (const int*)d_in[6];
    float*       out        = (float*)d_out;

    dim3 grid(B_DIM, BPB);   // 32 x 23 = 736 blocks = single wave @ occ 5
    hp_pairs_kernel<<<grid, THREADS>>>(seq, r, j_idx, h,
                                       r_half_raw, tau_hp_raw, max_dist, out);
}